// round 14
// baseline (speedup 1.0000x reference)
#include <cuda_runtime.h>
#include <cuda_fp16.h>
#include <math.h>

#define U_N 100000
#define I_N 50000
#define E_N 2000000
#define D_N 128
#define B_N 4096

#define CHUNK 1024
#define NCH_U ((U_N + CHUNK - 1) / CHUNK)   // 98
#define NCH_I ((I_N + CHUNK - 1) / CHUNK)   // 49

// ---------------- device scratch (static, allocation-free) ----------------
// fp16 rows: 128 half = 32 uint2 per row. Ping-pong buffers.
__device__ uint2 g_h_u[2][(size_t)U_N * 32];   // 2 x 25.6 MB
__device__ uint2 g_h_i[2][(size_t)I_N * 32];   // 2 x 12.8 MB
__device__ int   g_deg_u[U_N];
__device__ int   g_deg_i[I_N];
__device__ int   g_row_u[U_N + 1];
__device__ int   g_row_i[I_N + 1];
__device__ int   g_cur_u[U_N];
__device__ int   g_cur_i[I_N];
__device__ int   g_chunk_u[NCH_U];
__device__ int   g_chunk_i[NCH_I];
__device__ int2  g_adj_u[E_N];   // {item byte-offset (<<8), norm as duplicated half2}
__device__ int2  g_adj_i[E_N];   // {user byte-offset (<<8), norm as duplicated half2}
__device__ float g_acc_u[(size_t)B_N * D_N];
__device__ float g_acc_i[(size_t)B_N * D_N];

// ---------------- helpers ----------------
__device__ __forceinline__ __half2 u2h2(unsigned x) {
    return *reinterpret_cast<__half2*>(&x);
}

// ---------------- fused init: zero degrees + acc_init + loss zero ----------------
__global__ void init_kernel(const float4* __restrict__ user_feat,
                            const float4* __restrict__ item_feat,
                            const int* __restrict__ ui,
                            const int* __restrict__ ii,
                            float* __restrict__ loss_out,
                            int has_loss) {
    const int ZBLK = (U_N + 255) / 256;
    if (blockIdx.x < ZBLK) {
        int t = blockIdx.x * 256 + threadIdx.x;
        if (t < U_N) g_deg_u[t] = 0;
        if (t < I_N) g_deg_i[t] = 0;
        if (t == 0 && has_loss) *loss_out = 0.0f;
        return;
    }
    int t = (blockIdx.x - ZBLK) * 256 + threadIdx.x;  // over B*32
    if (t >= B_N * 32) return;
    int b = t >> 5;
    int d = t & 31;
    ((float4*)g_acc_u)[t] = user_feat[(size_t)ui[b] * 32 + d];
    ((float4*)g_acc_i)[t] = item_feat[(size_t)ii[b] * 32 + d];
}

// ---------------- degree (4 edges/thread, int4 index loads) ----------------
__global__ void degree_kernel(const int4* __restrict__ u_idx4,
                              const int4* __restrict__ i_idx4) {
    int t = blockIdx.x * blockDim.x + threadIdx.x;
    if (t >= E_N / 4) return;
    int4 u = u_idx4[t];
    int4 i = i_idx4[t];
    atomicAdd(&g_deg_u[u.x], 1); atomicAdd(&g_deg_u[u.y], 1);
    atomicAdd(&g_deg_u[u.z], 1); atomicAdd(&g_deg_u[u.w], 1);
    atomicAdd(&g_deg_i[i.x], 1); atomicAdd(&g_deg_i[i.y], 1);
    atomicAdd(&g_deg_i[i.z], 1); atomicAdd(&g_deg_i[i.w], 1);
}

// ---------------- scan phase A: per-chunk partial sums ----------------
__global__ void scan_partial_kernel() {
    bool isU = blockIdx.x < NCH_U;
    const int* deg = isU ? g_deg_u : g_deg_i;
    int* part      = isU ? g_chunk_u : g_chunk_i;
    int  c         = isU ? blockIdx.x : blockIdx.x - NCH_U;
    int  n         = isU ? U_N : I_N;

    int base = c * CHUNK + threadIdx.x * 4;
    int s = 0;
    #pragma unroll
    for (int j = 0; j < 4; j++) {
        int idx = base + j;
        if (idx < n) s += deg[idx];
    }
    #pragma unroll
    for (int o = 16; o > 0; o >>= 1) s += __shfl_down_sync(0xFFFFFFFFu, s, o);
    __shared__ int ws[8];
    if ((threadIdx.x & 31) == 0) ws[threadIdx.x >> 5] = s;
    __syncthreads();
    if (threadIdx.x < 8) {
        int v = ws[threadIdx.x];
        #pragma unroll
        for (int o = 4; o > 0; o >>= 1) v += __shfl_down_sync(0xFFu, v, o);
        if (threadIdx.x == 0) part[c] = v;
    }
}

// ---------------- scan phase B: one block scans both partial arrays ----------------
__global__ void scan_chunkoff_kernel() {
    __shared__ int buf[128];
    int t = threadIdx.x;

    int v = (t < NCH_U) ? g_chunk_u[t] : 0;
    buf[t] = v; __syncthreads();
    #pragma unroll
    for (int o = 1; o < 128; o <<= 1) {
        int x = (t >= o) ? buf[t - o] : 0;
        __syncthreads(); buf[t] += x; __syncthreads();
    }
    if (t < NCH_U) g_chunk_u[t] = buf[t] - v;
    __syncthreads();

    int v2 = (t < NCH_I) ? g_chunk_i[t] : 0;
    buf[t] = v2; __syncthreads();
    #pragma unroll
    for (int o = 1; o < 128; o <<= 1) {
        int x = (t >= o) ? buf[t - o] : 0;
        __syncthreads(); buf[t] += x; __syncthreads();
    }
    if (t < NCH_I) g_chunk_i[t] = buf[t] - v2;
    if (t == 0) { g_row_u[U_N] = E_N; g_row_i[I_N] = E_N; }
}

// ---------------- scan phase C: local scan + base; init cursors ----------------
__global__ void scan_final_kernel() {
    bool isU = blockIdx.x < NCH_U;
    const int* deg = isU ? g_deg_u : g_deg_i;
    int* row       = isU ? g_row_u : g_row_i;
    int* cur       = isU ? g_cur_u : g_cur_i;
    int  c         = isU ? blockIdx.x : blockIdx.x - NCH_U;
    int  n         = isU ? U_N : I_N;
    int  cbase     = isU ? g_chunk_u[c] : g_chunk_i[c];

    int base = c * CHUNK + threadIdx.x * 4;
    int d[4], e[4];
    int s = 0;
    #pragma unroll
    for (int j = 0; j < 4; j++) {
        int idx = base + j;
        d[j] = (idx < n) ? deg[idx] : 0;
        e[j] = s;
        s += d[j];
    }
    int lane = threadIdx.x & 31, w = threadIdx.x >> 5;
    int inc = s;
    #pragma unroll
    for (int o = 1; o < 32; o <<= 1) {
        int x = __shfl_up_sync(0xFFFFFFFFu, inc, o);
        if (lane >= o) inc += x;
    }
    __shared__ int ws[8];
    if (lane == 31) ws[w] = inc;
    __syncthreads();
    if (threadIdx.x < 8) {
        int v = ws[threadIdx.x];
        #pragma unroll
        for (int o = 1; o < 8; o <<= 1) {
            int x = __shfl_up_sync(0xFFu, v, o);
            if ((int)threadIdx.x >= o) v += x;
        }
        ws[threadIdx.x] = v;
    }
    __syncthreads();
    int excl = inc - s + (w > 0 ? ws[w - 1] : 0) + cbase;
    #pragma unroll
    for (int j = 0; j < 4; j++) {
        int idx = base + j;
        if (idx < n) { int r = excl + e[j]; row[idx] = r; cur[idx] = r; }
    }
}

// ---------------- fused fill (CSR adjacency, pre-shifted cols) + fp16 convert ----------------
#define FILL_BLOCKS_EXACT ((E_N / 4 + 255) / 256)         // 1954
#define CONV_BLOCKS (((U_N + I_N) * 32 + 255) / 256)      // 18750

__global__ void fillconv_kernel(const int4* __restrict__ u_idx4,
                                const int4* __restrict__ i_idx4,
                                const float4* __restrict__ user_feat,
                                const float4* __restrict__ item_feat) {
    if (blockIdx.x < FILL_BLOCKS_EXACT) {
        int t = blockIdx.x * 256 + threadIdx.x;
        if (t >= E_N / 4) return;
        int4 u4 = u_idx4[t];
        int4 i4 = i_idx4[t];
        #pragma unroll
        for (int j = 0; j < 4; j++) {
            int u = (j == 0) ? u4.x : (j == 1) ? u4.y : (j == 2) ? u4.z : u4.w;
            int i = (j == 0) ? i4.x : (j == 1) ? i4.y : (j == 2) ? i4.z : i4.w;
            float nf = rsqrtf((float)g_deg_u[u] * (float)g_deg_i[i]);
            __half2 h2 = __half2half2(__float2half_rn(nf));
            int nb = *reinterpret_cast<int*>(&h2);
            int pu = atomicAdd(&g_cur_u[u], 1);
            g_adj_u[pu] = make_int2(i << 8, nb);   // byte offset of 256B row
            int pi = atomicAdd(&g_cur_i[i], 1);
            g_adj_i[pi] = make_int2(u << 8, nb);
        }
        return;
    }
    // convert: one thread per 4 dims -> one uint2 (2 half2)
    int t = (blockIdx.x - FILL_BLOCKS_EXACT) * 256 + threadIdx.x;
    const int nu = U_N * 32;
    const int ni = I_N * 32;
    float4 v; uint2* dst; int o;
    if (t < nu)           { v = user_feat[t]; dst = g_h_u[0]; o = t; }
    else if (t < nu + ni) { o = t - nu; v = item_feat[o]; dst = g_h_i[0]; }
    else return;
    __half2 lo = __floats2half2_rn(v.x, v.y);
    __half2 hi = __floats2half2_rn(v.z, v.w);
    uint2 out;
    out.x = *reinterpret_cast<unsigned*>(&lo);
    out.y = *reinterpret_cast<unsigned*>(&hi);
    dst[o] = out;
}

// fma-accumulate one uint2 (2 half2, 4 dims) with weight n — NO converts
#define ACC_WORD(v, n)                          \
    do {                                        \
        a01 = __hfma2(u2h2((v).x), (n), a01);   \
        a23 = __hfma2(u2h2((v).y), (n), a23);   \
    } while (0)

// ---------------- gather: warp per row, lane owns one uint2 (4 dims) ----------------
__global__ void gather_kernel(const uint2* __restrict__ s_u,
                              const uint2* __restrict__ s_i,
                              uint2* __restrict__ d_u,
                              uint2* __restrict__ d_i,
                              const int* __restrict__ ui,
                              const int* __restrict__ ii,
                              float acc_coef) {
    int w = (blockIdx.x * blockDim.x + threadIdx.x) >> 5;
    int lane = threadIdx.x & 31;

    if (w >= U_N + I_N) {
        int b = w - (U_N + I_N);
        if (b >= B_N || acc_coef == 0.0f) return;
        float c = acc_coef;
        int t = b * 32 + lane;
        uint2 q = s_u[(size_t)ui[b] * 32 + lane];
        float2 p = __half22float2(u2h2(q.x));
        float2 r = __half22float2(u2h2(q.y));
        float4 a = ((float4*)g_acc_u)[t];
        a.x += c * p.x; a.y += c * p.y; a.z += c * r.x; a.w += c * r.y;
        ((float4*)g_acc_u)[t] = a;
        uint2 q2 = s_i[(size_t)ii[b] * 32 + lane];
        p = __half22float2(u2h2(q2.x));
        r = __half22float2(u2h2(q2.y));
        float4 ai = ((float4*)g_acc_i)[t];
        ai.x += c * p.x; ai.y += c * p.y; ai.z += c * r.x; ai.w += c * r.y;
        ((float4*)g_acc_i)[t] = ai;
        return;
    }

    const int* rp; const int2* adj;
    const uint2* src; const uint2* self; uint2* dst; int d;
    if (w < U_N) {
        d = w; rp = g_row_u; adj = g_adj_u;
        src = s_i; self = s_u; dst = d_u;
    } else {
        d = w - U_N; rp = g_row_i; adj = g_adj_i;
        src = s_u; self = s_i; dst = d_i;
    }

    int start = rp[d];
    int end   = rp[d + 1];

    // per-lane base pointer: each neighbor load is base + pre-shifted offset
    const char* lane_base = reinterpret_cast<const char*>(src) + ((unsigned)lane << 3);
    #define LDN(off) (*reinterpret_cast<const uint2*>(lane_base + (unsigned)(off)))

    uint2 sv = self[(size_t)d * 32 + lane];
    __half2 a01 = u2h2(sv.x);
    __half2 a23 = u2h2(sv.y);

    int k = start;
    if ((k & 1) && k < end) {   // peel to even k for aligned int4 adjacency loads
        int2 e0 = adj[k];
        uint2 v0 = LDN(e0.x);
        ACC_WORD(v0, *reinterpret_cast<__half2*>(&e0.y));
        k++;
    }
    // 8-edge unrolled main loop: 4x LDG.128 adj + 8x LDG.64 rows in flight
    for (; k + 8 <= end; k += 8) {
        const int4* p4 = reinterpret_cast<const int4*>(adj + k);
        int4 A = p4[0];
        int4 B = p4[1];
        int4 C = p4[2];
        int4 D = p4[3];
        uint2 v0 = LDN(A.x);
        uint2 v1 = LDN(A.z);
        uint2 v2 = LDN(B.x);
        uint2 v3 = LDN(B.z);
        uint2 v4 = LDN(C.x);
        uint2 v5 = LDN(C.z);
        uint2 v6 = LDN(D.x);
        uint2 v7 = LDN(D.z);
        ACC_WORD(v0, *reinterpret_cast<__half2*>(&A.y));
        ACC_WORD(v1, *reinterpret_cast<__half2*>(&A.w));
        ACC_WORD(v2, *reinterpret_cast<__half2*>(&B.y));
        ACC_WORD(v3, *reinterpret_cast<__half2*>(&B.w));
        ACC_WORD(v4, *reinterpret_cast<__half2*>(&C.y));
        ACC_WORD(v5, *reinterpret_cast<__half2*>(&C.w));
        ACC_WORD(v6, *reinterpret_cast<__half2*>(&D.y));
        ACC_WORD(v7, *reinterpret_cast<__half2*>(&D.w));
    }
    if (k + 4 <= end) {
        const int4* p4 = reinterpret_cast<const int4*>(adj + k);
        int4 A = p4[0];
        int4 B = p4[1];
        uint2 v0 = LDN(A.x);
        uint2 v1 = LDN(A.z);
        uint2 v2 = LDN(B.x);
        uint2 v3 = LDN(B.z);
        ACC_WORD(v0, *reinterpret_cast<__half2*>(&A.y));
        ACC_WORD(v1, *reinterpret_cast<__half2*>(&A.w));
        ACC_WORD(v2, *reinterpret_cast<__half2*>(&B.y));
        ACC_WORD(v3, *reinterpret_cast<__half2*>(&B.w));
        k += 4;
    }
    for (; k < end; k++) {
        int2 e0 = adj[k];
        uint2 v0 = LDN(e0.x);
        ACC_WORD(v0, *reinterpret_cast<__half2*>(&e0.y));
    }
    #undef LDN

    uint2 out;
    out.x = *reinterpret_cast<unsigned*>(&a01);
    out.y = *reinterpret_cast<unsigned*>(&a23);
    dst[(size_t)d * 32 + lane] = out;
}

// ---------------- fused final: last-layer acc + dot + sigmoid + BCE ----------------
__global__ void final_kernel(const uint2* __restrict__ h3_u,
                             const uint2* __restrict__ h3_i,
                             const int* __restrict__ ui,
                             const int* __restrict__ ii,
                             const float* __restrict__ labels,
                             float* __restrict__ pred_out,
                             float* __restrict__ loss_out,
                             int has_loss) {
    int b = (blockIdx.x * blockDim.x + threadIdx.x) >> 5;
    int lane = threadIdx.x & 31;
    if (b >= B_N) return;

    const float c = 0.25f;   // layer-3 coefficient
    int t = b * 32 + lane;

    float4 a = ((const float4*)g_acc_u)[t];
    uint2 q = h3_u[(size_t)ui[b] * 32 + lane];
    float2 p = __half22float2(u2h2(q.x));
    float2 r = __half22float2(u2h2(q.y));
    a.x += c * p.x; a.y += c * p.y; a.z += c * r.x; a.w += c * r.y;

    float4 ai = ((const float4*)g_acc_i)[t];
    uint2 q2 = h3_i[(size_t)ii[b] * 32 + lane];
    p = __half22float2(u2h2(q2.x));
    r = __half22float2(u2h2(q2.y));
    ai.x += c * p.x; ai.y += c * p.y; ai.z += c * r.x; ai.w += c * r.y;

    float s = a.x * ai.x + a.y * ai.y + a.z * ai.z + a.w * ai.w;
    #pragma unroll
    for (int o = 16; o > 0; o >>= 1)
        s += __shfl_down_sync(0xFFFFFFFFu, s, o);

    if (lane == 0) {
        float z = 1.0f / (1.0f + expf(-s));
        pred_out[b] = z;
        if (has_loss) {
            float lbl = labels[b];
            float term = fmaxf(z, 0.0f) - z * lbl + log1pf(expf(-fabsf(z)));
            atomicAdd(loss_out, term * (1.0f / (float)B_N));
        }
    }
}

// ---------------- host launch ----------------
extern "C" void kernel_launch(void* const* d_in, const int* in_sizes, int n_in,
                              void* d_out, int out_size) {
    const float* user_feat = (const float*)d_in[0];
    const float* item_feat = (const float*)d_in[1];
    const int*   u_idx     = (const int*)d_in[2];
    const int*   i_idx     = (const int*)d_in[3];
    const int*   ui        = (const int*)d_in[4];
    const int*   ii        = (const int*)d_in[5];
    const float* labels    = (const float*)d_in[6];

    float* out = (float*)d_out;
    int has_loss = (out_size > B_N) ? 1 : 0;
    float* pred_out = out + (out_size - B_N);
    float* loss_out = out;

    uint2 *hu_base, *hi_base;
    cudaGetSymbolAddress((void**)&hu_base, g_h_u);
    cudaGetSymbolAddress((void**)&hi_base, g_h_i);
    uint2* hu[2] = { hu_base, hu_base + (size_t)U_N * 32 };
    uint2* hi[2] = { hi_base, hi_base + (size_t)I_N * 32 };

    const int T = 256;
    const int ZBLK = (U_N + 255) / 256;
    const int init_blocks = ZBLK + (B_N * 32 + 255) / 256;
    const int deg_blocks = (E_N / 4 + T - 1) / T;
    const int fillconv_blocks = FILL_BLOCKS_EXACT + CONV_BLOCKS;
    const int gather_blocks = ((U_N + I_N + B_N) * 32 + T - 1) / T;

    // 1) fused init (zero degrees, acc layer-0 from exact fp32, zero loss)
    init_kernel<<<init_blocks, T>>>((const float4*)user_feat,
                                    (const float4*)item_feat,
                                    ui, ii, loss_out, has_loss);
    // 2) degrees
    degree_kernel<<<deg_blocks, T>>>((const int4*)u_idx, (const int4*)i_idx);
    // 3) row-pointer scan
    scan_partial_kernel<<<NCH_U + NCH_I, 256>>>();
    scan_chunkoff_kernel<<<1, 128>>>();
    scan_final_kernel<<<NCH_U + NCH_I, 256>>>();
    // 4) fused CSR fill (pre-shifted byte-offset columns) + fp16 convert
    fillconv_kernel<<<fillconv_blocks, T>>>((const int4*)u_idx, (const int4*)i_idx,
                                            (const float4*)user_feat,
                                            (const float4*)item_feat);

    // 5) three propagation layers; each also applies the previous layer's acc
    const float coefs[3] = { 0.5f, 1.0f / 3.0f, 0.25f };
    int cur = 0;
    for (int l = 0; l < 3; l++) {
        int nxt = 1 - cur;
        float prev_coef = (l == 0) ? 0.0f : coefs[l - 1];
        gather_kernel<<<gather_blocks, T>>>(hu[cur], hi[cur],
                                            hu[nxt], hi[nxt],
                                            ui, ii, prev_coef);
        cur = nxt;
    }

    // 6) fused final: layer-3 acc + dot + sigmoid + BCE
    final_kernel<<<(B_N * 32 + T - 1) / T, T>>>(hu[cur], hi[cur],
                                                ui, ii, labels,
                                                pred_out, loss_out, has_loss);
}

// round 15
// speedup vs baseline: 1.5652x; 1.5652x over previous
#include <cuda_runtime.h>
#include <cuda_fp16.h>
#include <math.h>

#define U_N 100000
#define I_N 50000
#define E_N 2000000
#define D_N 128
#define B_N 4096

#define FP8_SCALE 256.0f
#define FP8_INV   (1.0f / 256.0f)

#define CHUNK 1024
#define NCH_U ((U_N + CHUNK - 1) / CHUNK)   // 98
#define NCH_I ((I_N + CHUNK - 1) / CHUNK)   // 49

// ---------------- device scratch (static, allocation-free) ----------------
__device__ unsigned g_f8_u[2][(size_t)U_N * 32];  // fp8 rows ping-pong (12.8 MB each)
__device__ unsigned g_f8_i[2][(size_t)I_N * 32];  // (6.4 MB each)
__device__ int   g_deg_u[U_N];
__device__ int   g_deg_i[I_N];
__device__ int   g_row_u[U_N + 1];
__device__ int   g_row_i[I_N + 1];
__device__ int   g_cur_u[U_N];
__device__ int   g_cur_i[I_N];
__device__ int   g_chunk_u[NCH_U];
__device__ int   g_chunk_i[NCH_I];
__device__ int2  g_adj_u[E_N];   // {item byte-offset (<<7), norm as duplicated half2}
__device__ int2  g_adj_i[E_N];   // {user byte-offset (<<7), norm as duplicated half2}
__device__ float g_acc_u[(size_t)B_N * D_N];
__device__ float g_acc_i[(size_t)B_N * D_N];

// ---------------- fp8 helpers (fast packed class) ----------------
__device__ __forceinline__ __half2 e4m3x2_to_h2(unsigned short s) {
    unsigned r;
    asm("cvt.rn.f16x2.e4m3x2 %0, %1;" : "=r"(r) : "h"(s));
    return *reinterpret_cast<__half2*>(&r);
}
__device__ __forceinline__ unsigned short h2_to_e4m3x2(__half2 h) {
    unsigned short s;
    unsigned hr = *reinterpret_cast<unsigned*>(&h);
    asm("cvt.rn.satfinite.e4m3x2.f16x2 %0, %1;" : "=h"(s) : "r"(hr));
    return s;
}
__device__ __forceinline__ unsigned pack_f8x4(__half2 lo, __half2 hi) {
    return (unsigned)h2_to_e4m3x2(lo) | ((unsigned)h2_to_e4m3x2(hi) << 16);
}

// fma-accumulate one fp8x4 word with weight n into a01/a23
#define ACC_WORD(v, n)                                                          \
    do {                                                                        \
        a01 = __hfma2(e4m3x2_to_h2((unsigned short)((v) & 0xFFFFu)), (n), a01); \
        a23 = __hfma2(e4m3x2_to_h2((unsigned short)((v) >> 16)),     (n), a23); \
    } while (0)

// CSR row gather core: a01/a23 += sum over [start,end) of norm * src_row word.
// lane_base = src byte-base + lane*4; adj entries hold pre-shifted byte offsets.
__device__ __forceinline__ void row_gather(const int2* __restrict__ adj,
                                           const char* lane_base,
                                           int start, int end,
                                           __half2& a01, __half2& a23) {
    #define LDN(off) (*reinterpret_cast<const unsigned*>(lane_base + (unsigned)(off)))
    int k = start;
    if ((k & 1) && k < end) {
        int2 e0 = adj[k];
        unsigned v0 = LDN(e0.x);
        ACC_WORD(v0, *reinterpret_cast<__half2*>(&e0.y));
        k++;
    }
    for (; k + 8 <= end; k += 8) {
        const int4* p4 = reinterpret_cast<const int4*>(adj + k);
        int4 A = p4[0];
        int4 B = p4[1];
        int4 C = p4[2];
        int4 D = p4[3];
        unsigned v0 = LDN(A.x);
        unsigned v1 = LDN(A.z);
        unsigned v2 = LDN(B.x);
        unsigned v3 = LDN(B.z);
        unsigned v4 = LDN(C.x);
        unsigned v5 = LDN(C.z);
        unsigned v6 = LDN(D.x);
        unsigned v7 = LDN(D.z);
        ACC_WORD(v0, *reinterpret_cast<__half2*>(&A.y));
        ACC_WORD(v1, *reinterpret_cast<__half2*>(&A.w));
        ACC_WORD(v2, *reinterpret_cast<__half2*>(&B.y));
        ACC_WORD(v3, *reinterpret_cast<__half2*>(&B.w));
        ACC_WORD(v4, *reinterpret_cast<__half2*>(&C.y));
        ACC_WORD(v5, *reinterpret_cast<__half2*>(&C.w));
        ACC_WORD(v6, *reinterpret_cast<__half2*>(&D.y));
        ACC_WORD(v7, *reinterpret_cast<__half2*>(&D.w));
    }
    if (k + 4 <= end) {
        const int4* p4 = reinterpret_cast<const int4*>(adj + k);
        int4 A = p4[0];
        int4 B = p4[1];
        unsigned v0 = LDN(A.x);
        unsigned v1 = LDN(A.z);
        unsigned v2 = LDN(B.x);
        unsigned v3 = LDN(B.z);
        ACC_WORD(v0, *reinterpret_cast<__half2*>(&A.y));
        ACC_WORD(v1, *reinterpret_cast<__half2*>(&A.w));
        ACC_WORD(v2, *reinterpret_cast<__half2*>(&B.y));
        ACC_WORD(v3, *reinterpret_cast<__half2*>(&B.w));
        k += 4;
    }
    for (; k < end; k++) {
        int2 e0 = adj[k];
        unsigned v0 = LDN(e0.x);
        ACC_WORD(v0, *reinterpret_cast<__half2*>(&e0.y));
    }
    #undef LDN
}

// ---------------- fused init: zero degrees + acc_init + loss zero ----------------
__global__ void init_kernel(const float4* __restrict__ user_feat,
                            const float4* __restrict__ item_feat,
                            const int* __restrict__ ui,
                            const int* __restrict__ ii,
                            float* __restrict__ loss_out,
                            int has_loss) {
    const int ZBLK = (U_N + 255) / 256;
    if (blockIdx.x < ZBLK) {
        int t = blockIdx.x * 256 + threadIdx.x;
        if (t < U_N) g_deg_u[t] = 0;
        if (t < I_N) g_deg_i[t] = 0;
        if (t == 0 && has_loss) *loss_out = 0.0f;
        return;
    }
    int t = (blockIdx.x - ZBLK) * 256 + threadIdx.x;  // over B*32
    if (t >= B_N * 32) return;
    int b = t >> 5;
    int d = t & 31;
    ((float4*)g_acc_u)[t] = user_feat[(size_t)ui[b] * 32 + d];
    ((float4*)g_acc_i)[t] = item_feat[(size_t)ii[b] * 32 + d];
}

// ---------------- degree (4 edges/thread, int4 index loads) ----------------
__global__ void degree_kernel(const int4* __restrict__ u_idx4,
                              const int4* __restrict__ i_idx4) {
    int t = blockIdx.x * blockDim.x + threadIdx.x;
    if (t >= E_N / 4) return;
    int4 u = u_idx4[t];
    int4 i = i_idx4[t];
    atomicAdd(&g_deg_u[u.x], 1); atomicAdd(&g_deg_u[u.y], 1);
    atomicAdd(&g_deg_u[u.z], 1); atomicAdd(&g_deg_u[u.w], 1);
    atomicAdd(&g_deg_i[i.x], 1); atomicAdd(&g_deg_i[i.y], 1);
    atomicAdd(&g_deg_i[i.z], 1); atomicAdd(&g_deg_i[i.w], 1);
}

// ---------------- scan phase A: per-chunk partial sums ----------------
__global__ void scan_partial_kernel() {
    bool isU = blockIdx.x < NCH_U;
    const int* deg = isU ? g_deg_u : g_deg_i;
    int* part      = isU ? g_chunk_u : g_chunk_i;
    int  c         = isU ? blockIdx.x : blockIdx.x - NCH_U;
    int  n         = isU ? U_N : I_N;

    int base = c * CHUNK + threadIdx.x * 4;
    int s = 0;
    #pragma unroll
    for (int j = 0; j < 4; j++) {
        int idx = base + j;
        if (idx < n) s += deg[idx];
    }
    #pragma unroll
    for (int o = 16; o > 0; o >>= 1) s += __shfl_down_sync(0xFFFFFFFFu, s, o);
    __shared__ int ws[8];
    if ((threadIdx.x & 31) == 0) ws[threadIdx.x >> 5] = s;
    __syncthreads();
    if (threadIdx.x < 8) {
        int v = ws[threadIdx.x];
        #pragma unroll
        for (int o = 4; o > 0; o >>= 1) v += __shfl_down_sync(0xFFu, v, o);
        if (threadIdx.x == 0) part[c] = v;
    }
}

// ---------------- scan phase B: one block scans both partial arrays ----------------
__global__ void scan_chunkoff_kernel() {
    __shared__ int buf[128];
    int t = threadIdx.x;

    int v = (t < NCH_U) ? g_chunk_u[t] : 0;
    buf[t] = v; __syncthreads();
    #pragma unroll
    for (int o = 1; o < 128; o <<= 1) {
        int x = (t >= o) ? buf[t - o] : 0;
        __syncthreads(); buf[t] += x; __syncthreads();
    }
    if (t < NCH_U) g_chunk_u[t] = buf[t] - v;
    __syncthreads();

    int v2 = (t < NCH_I) ? g_chunk_i[t] : 0;
    buf[t] = v2; __syncthreads();
    #pragma unroll
    for (int o = 1; o < 128; o <<= 1) {
        int x = (t >= o) ? buf[t - o] : 0;
        __syncthreads(); buf[t] += x; __syncthreads();
    }
    if (t < NCH_I) g_chunk_i[t] = buf[t] - v2;
    if (t == 0) { g_row_u[U_N] = E_N; g_row_i[I_N] = E_N; }
}

// ---------------- scan phase C: local scan + base; init cursors ----------------
__global__ void scan_final_kernel() {
    bool isU = blockIdx.x < NCH_U;
    const int* deg = isU ? g_deg_u : g_deg_i;
    int* row       = isU ? g_row_u : g_row_i;
    int* cur       = isU ? g_cur_u : g_cur_i;
    int  c         = isU ? blockIdx.x : blockIdx.x - NCH_U;
    int  n         = isU ? U_N : I_N;
    int  cbase     = isU ? g_chunk_u[c] : g_chunk_i[c];

    int base = c * CHUNK + threadIdx.x * 4;
    int d[4], e[4];
    int s = 0;
    #pragma unroll
    for (int j = 0; j < 4; j++) {
        int idx = base + j;
        d[j] = (idx < n) ? deg[idx] : 0;
        e[j] = s;
        s += d[j];
    }
    int lane = threadIdx.x & 31, w = threadIdx.x >> 5;
    int inc = s;
    #pragma unroll
    for (int o = 1; o < 32; o <<= 1) {
        int x = __shfl_up_sync(0xFFFFFFFFu, inc, o);
        if (lane >= o) inc += x;
    }
    __shared__ int ws[8];
    if (lane == 31) ws[w] = inc;
    __syncthreads();
    if (threadIdx.x < 8) {
        int v = ws[threadIdx.x];
        #pragma unroll
        for (int o = 1; o < 8; o <<= 1) {
            int x = __shfl_up_sync(0xFFu, v, o);
            if ((int)threadIdx.x >= o) v += x;
        }
        ws[threadIdx.x] = v;
    }
    __syncthreads();
    int excl = inc - s + (w > 0 ? ws[w - 1] : 0) + cbase;
    #pragma unroll
    for (int j = 0; j < 4; j++) {
        int idx = base + j;
        if (idx < n) { int r = excl + e[j]; row[idx] = r; cur[idx] = r; }
    }
}

// ---------------- fused fill (CSR adjacency, pre-shifted cols) + fp8 convert ----------------
#define FILL_BLOCKS_EXACT ((E_N / 4 + 255) / 256)         // 1954
#define CONV_BLOCKS (((U_N + I_N) * 32 + 255) / 256)      // 18750

__global__ void fillconv_kernel(const int4* __restrict__ u_idx4,
                                const int4* __restrict__ i_idx4,
                                const float4* __restrict__ user_feat,
                                const float4* __restrict__ item_feat) {
    if (blockIdx.x < FILL_BLOCKS_EXACT) {
        int t = blockIdx.x * 256 + threadIdx.x;
        if (t >= E_N / 4) return;
        int4 u4 = u_idx4[t];
        int4 i4 = i_idx4[t];
        #pragma unroll
        for (int j = 0; j < 4; j++) {
            int u = (j == 0) ? u4.x : (j == 1) ? u4.y : (j == 2) ? u4.z : u4.w;
            int i = (j == 0) ? i4.x : (j == 1) ? i4.y : (j == 2) ? i4.z : i4.w;
            float nf = rsqrtf((float)g_deg_u[u] * (float)g_deg_i[i]);
            __half2 h2 = __half2half2(__float2half_rn(nf));
            int nb = *reinterpret_cast<int*>(&h2);
            int pu = atomicAdd(&g_cur_u[u], 1);
            g_adj_u[pu] = make_int2(i << 7, nb);   // byte offset of row
            int pi = atomicAdd(&g_cur_i[i], 1);
            g_adj_i[pi] = make_int2(u << 7, nb);
        }
        return;
    }
    int t = (blockIdx.x - FILL_BLOCKS_EXACT) * 256 + threadIdx.x;
    const int nu = U_N * 32;
    const int ni = I_N * 32;
    float4 v; unsigned* dst; int o;
    if (t < nu)           { v = user_feat[t]; dst = g_f8_u[0]; o = t; }
    else if (t < nu + ni) { o = t - nu; v = item_feat[o]; dst = g_f8_i[0]; }
    else return;
    __half2 lo = __floats2half2_rn(v.x * FP8_SCALE, v.y * FP8_SCALE);
    __half2 hi = __floats2half2_rn(v.z * FP8_SCALE, v.w * FP8_SCALE);
    dst[o] = pack_f8x4(lo, hi);
}

// ---------------- gather: warp per row (R12 layout); fused acc warps ----------------
__global__ void gather_kernel(const unsigned* __restrict__ s8_u,
                              const unsigned* __restrict__ s8_i,
                              unsigned* __restrict__ d8_u,
                              unsigned* __restrict__ d8_i,
                              const int* __restrict__ ui,
                              const int* __restrict__ ii,
                              float acc_coef) {
    int w = (blockIdx.x * blockDim.x + threadIdx.x) >> 5;
    int lane = threadIdx.x & 31;

    if (w >= U_N + I_N) {
        int b = w - (U_N + I_N);
        if (b >= B_N || acc_coef == 0.0f) return;
        float c = acc_coef * FP8_INV;
        int t = b * 32 + lane;
        unsigned q = s8_u[(size_t)ui[b] * 32 + lane];
        float2 p = __half22float2(e4m3x2_to_h2((unsigned short)(q & 0xFFFFu)));
        float2 r = __half22float2(e4m3x2_to_h2((unsigned short)(q >> 16)));
        float4 a = ((float4*)g_acc_u)[t];
        a.x += c * p.x; a.y += c * p.y; a.z += c * r.x; a.w += c * r.y;
        ((float4*)g_acc_u)[t] = a;
        unsigned q2 = s8_i[(size_t)ii[b] * 32 + lane];
        p = __half22float2(e4m3x2_to_h2((unsigned short)(q2 & 0xFFFFu)));
        r = __half22float2(e4m3x2_to_h2((unsigned short)(q2 >> 16)));
        float4 ai = ((float4*)g_acc_i)[t];
        ai.x += c * p.x; ai.y += c * p.y; ai.z += c * r.x; ai.w += c * r.y;
        ((float4*)g_acc_i)[t] = ai;
        return;
    }

    const int* rp; const int2* adj;
    const unsigned* src; const unsigned* self; unsigned* dst; int d;
    if (w < U_N) {
        d = w; rp = g_row_u; adj = g_adj_u;
        src = s8_i; self = s8_u; dst = d8_u;
    } else {
        d = w - U_N; rp = g_row_i; adj = g_adj_i;
        src = s8_u; self = s8_i; dst = d8_i;
    }

    int start = rp[d];
    int end   = rp[d + 1];
    const char* lane_base = reinterpret_cast<const char*>(src) + ((unsigned)lane << 2);

    unsigned sv = self[(size_t)d * 32 + lane];
    __half2 a01 = e4m3x2_to_h2((unsigned short)(sv & 0xFFFFu));
    __half2 a23 = e4m3x2_to_h2((unsigned short)(sv >> 16));

    row_gather(adj, lane_base, start, end, a01, a23);

    dst[(size_t)d * 32 + lane] = pack_f8x4(a01, a23);
}

// ---------------- fused final: on-the-fly layer-3 rows + layers 2,3 acc + BCE ----------------
// One warp per batch element b:
//   row3_u[ui[b]] = h2_u[ui[b]] + sum norm*h2_i[nbr]   (computed in registers)
//   ue = acc_u[b] (layers 0..1) + (1/3)*h2_u[ui[b]] + (1/4)*row3_u
//   likewise items; then dot, sigmoid, BCE.
__global__ void final_kernel(const unsigned* __restrict__ h2_u,
                             const unsigned* __restrict__ h2_i,
                             const int* __restrict__ ui,
                             const int* __restrict__ ii,
                             const float* __restrict__ labels,
                             float* __restrict__ pred_out,
                             float* __restrict__ loss_out,
                             int has_loss) {
    int b = (blockIdx.x * blockDim.x + threadIdx.x) >> 5;
    int lane = threadIdx.x & 31;
    if (b >= B_N) return;

    const float c2 = (1.0f / 3.0f) * FP8_INV;
    const float c3 = 0.25f * FP8_INV;
    int t = b * 32 + lane;

    // ---- user side ----
    int ru = ui[b];
    unsigned svu = h2_u[(size_t)ru * 32 + lane];
    __half2 a01 = e4m3x2_to_h2((unsigned short)(svu & 0xFFFFu));
    __half2 a23 = e4m3x2_to_h2((unsigned short)(svu >> 16));
    float2 su0 = __half22float2(a01);   // self (h2) floats for the 1/3 term
    float2 su1 = __half22float2(a23);
    {
        const char* lane_base = reinterpret_cast<const char*>(h2_i) + ((unsigned)lane << 2);
        row_gather(g_adj_u, lane_base, g_row_u[ru], g_row_u[ru + 1], a01, a23);
    }
    float2 r0 = __half22float2(a01);    // row3 floats
    float2 r1 = __half22float2(a23);
    float4 au = ((const float4*)g_acc_u)[t];
    au.x += c2 * su0.x + c3 * r0.x;
    au.y += c2 * su0.y + c3 * r0.y;
    au.z += c2 * su1.x + c3 * r1.x;
    au.w += c2 * su1.y + c3 * r1.y;

    // ---- item side ----
    int ri = ii[b];
    unsigned svi = h2_i[(size_t)ri * 32 + lane];
    a01 = e4m3x2_to_h2((unsigned short)(svi & 0xFFFFu));
    a23 = e4m3x2_to_h2((unsigned short)(svi >> 16));
    float2 si0 = __half22float2(a01);
    float2 si1 = __half22float2(a23);
    {
        const char* lane_base = reinterpret_cast<const char*>(h2_u) + ((unsigned)lane << 2);
        row_gather(g_adj_i, lane_base, g_row_i[ri], g_row_i[ri + 1], a01, a23);
    }
    r0 = __half22float2(a01);
    r1 = __half22float2(a23);
    float4 ai = ((const float4*)g_acc_i)[t];
    ai.x += c2 * si0.x + c3 * r0.x;
    ai.y += c2 * si0.y + c3 * r0.y;
    ai.z += c2 * si1.x + c3 * r1.x;
    ai.w += c2 * si1.y + c3 * r1.y;

    // ---- dot + sigmoid + BCE ----
    float s = au.x * ai.x + au.y * ai.y + au.z * ai.z + au.w * ai.w;
    #pragma unroll
    for (int o = 16; o > 0; o >>= 1)
        s += __shfl_down_sync(0xFFFFFFFFu, s, o);

    if (lane == 0) {
        float z = 1.0f / (1.0f + expf(-s));
        pred_out[b] = z;
        if (has_loss) {
            float lbl = labels[b];
            float term = fmaxf(z, 0.0f) - z * lbl + log1pf(expf(-fabsf(z)));
            atomicAdd(loss_out, term * (1.0f / (float)B_N));
        }
    }
}

// ---------------- host launch ----------------
extern "C" void kernel_launch(void* const* d_in, const int* in_sizes, int n_in,
                              void* d_out, int out_size) {
    const float* user_feat = (const float*)d_in[0];
    const float* item_feat = (const float*)d_in[1];
    const int*   u_idx     = (const int*)d_in[2];
    const int*   i_idx     = (const int*)d_in[3];
    const int*   ui        = (const int*)d_in[4];
    const int*   ii        = (const int*)d_in[5];
    const float* labels    = (const float*)d_in[6];

    float* out = (float*)d_out;
    int has_loss = (out_size > B_N) ? 1 : 0;
    float* pred_out = out + (out_size - B_N);
    float* loss_out = out;

    unsigned *hu_base, *hi_base;
    cudaGetSymbolAddress((void**)&hu_base, g_f8_u);
    cudaGetSymbolAddress((void**)&hi_base, g_f8_i);
    unsigned* hu[2] = { hu_base, hu_base + (size_t)U_N * 32 };
    unsigned* hi[2] = { hi_base, hi_base + (size_t)I_N * 32 };

    const int T = 256;
    const int ZBLK = (U_N + 255) / 256;
    const int init_blocks = ZBLK + (B_N * 32 + 255) / 256;
    const int deg_blocks = (E_N / 4 + T - 1) / T;
    const int fillconv_blocks = FILL_BLOCKS_EXACT + CONV_BLOCKS;
    const int gather_blocks = ((U_N + I_N + B_N) * 32 + T - 1) / T;

    // 1) fused init (zero degrees, acc layer-0 from exact fp32, zero loss)
    init_kernel<<<init_blocks, T>>>((const float4*)user_feat,
                                    (const float4*)item_feat,
                                    ui, ii, loss_out, has_loss);
    // 2) degrees
    degree_kernel<<<deg_blocks, T>>>((const int4*)u_idx, (const int4*)i_idx);
    // 3) row-pointer scan
    scan_partial_kernel<<<NCH_U + NCH_I, 256>>>();
    scan_chunkoff_kernel<<<1, 128>>>();
    scan_final_kernel<<<NCH_U + NCH_I, 256>>>();
    // 4) fused CSR fill (pre-shifted byte-offset columns) + fp8 convert
    fillconv_kernel<<<fillconv_blocks, T>>>((const int4*)u_idx, (const int4*)i_idx,
                                            (const float4*)user_feat,
                                            (const float4*)item_feat);

    // 5) TWO full propagation layers (h1, h2); layer-1 acc fused into gather #2
    gather_kernel<<<gather_blocks, T>>>(hu[0], hi[0], hu[1], hi[1],
                                        ui, ii, 0.0f);
    gather_kernel<<<gather_blocks, T>>>(hu[1], hi[1], hu[0], hi[0],
                                        ui, ii, 0.5f);
    // hu[0]/hi[0] now hold h2

    // 6) fused final: layer-2 acc + on-the-fly layer-3 rows + dot + sigmoid + BCE
    final_kernel<<<(B_N * 32 + T - 1) / T, T>>>(hu[0], hi[0],
                                                ui, ii, labels,
                                                pred_out, loss_out, has_loss);
}

// round 16
// speedup vs baseline: 1.5772x; 1.0076x over previous
#include <cuda_runtime.h>
#include <cuda_fp16.h>
#include <math.h>

#define U_N 100000
#define I_N 50000
#define E_N 2000000
#define D_N 128
#define B_N 4096

#define FP8_SCALE 256.0f
#define FP8_INV   (1.0f / 256.0f)

#define CHUNK 1024
#define NCH_U ((U_N + CHUNK - 1) / CHUNK)   // 98
#define NCH_I ((I_N + CHUNK - 1) / CHUNK)   // 49
#define NBLK  (NCH_U + NCH_I)               // 147 (<= 148 SMs: co-resident)

// ---------------- device scratch (static, allocation-free) ----------------
__device__ unsigned g_f8_u[2][(size_t)U_N * 32];  // fp8 rows ping-pong (12.8 MB each)
__device__ unsigned g_f8_i[2][(size_t)I_N * 32];  // (6.4 MB each)
__device__ int   g_deg_u[U_N];
__device__ int   g_deg_i[I_N];
__device__ int   g_row_u[U_N + 1];
__device__ int   g_row_i[I_N + 1];
__device__ int   g_cur_u[U_N];
__device__ int   g_cur_i[I_N];
__device__ int   g_chunk_u[NCH_U];
__device__ int   g_chunk_i[NCH_I];
__device__ int2  g_adj_u[E_N];   // {item byte-offset (<<7), norm as duplicated half2}
__device__ int2  g_adj_i[E_N];   // {user byte-offset (<<7), norm as duplicated half2}
__device__ float g_acc_u[(size_t)B_N * D_N];
__device__ float g_acc_i[(size_t)B_N * D_N];
__device__ unsigned g_cnt[2];    // grid-barrier counters (zeroed by init each launch)

// ---------------- fp8 helpers (fast packed class) ----------------
__device__ __forceinline__ __half2 e4m3x2_to_h2(unsigned short s) {
    unsigned r;
    asm("cvt.rn.f16x2.e4m3x2 %0, %1;" : "=r"(r) : "h"(s));
    return *reinterpret_cast<__half2*>(&r);
}
__device__ __forceinline__ unsigned short h2_to_e4m3x2(__half2 h) {
    unsigned short s;
    unsigned hr = *reinterpret_cast<unsigned*>(&h);
    asm("cvt.rn.satfinite.e4m3x2.f16x2 %0, %1;" : "=h"(s) : "r"(hr));
    return s;
}
__device__ __forceinline__ unsigned pack_f8x4(__half2 lo, __half2 hi) {
    return (unsigned)h2_to_e4m3x2(lo) | ((unsigned)h2_to_e4m3x2(hi) << 16);
}

// fma-accumulate one fp8x4 word with weight n into a01/a23
#define ACC_WORD(v, n)                                                          \
    do {                                                                        \
        a01 = __hfma2(e4m3x2_to_h2((unsigned short)((v) & 0xFFFFu)), (n), a01); \
        a23 = __hfma2(e4m3x2_to_h2((unsigned short)((v) >> 16)),     (n), a23); \
    } while (0)

// CSR row gather core: a01/a23 += sum over [start,end) of norm * src_row word.
__device__ __forceinline__ void row_gather(const int2* __restrict__ adj,
                                           const char* lane_base,
                                           int start, int end,
                                           __half2& a01, __half2& a23) {
    #define LDN(off) (*reinterpret_cast<const unsigned*>(lane_base + (unsigned)(off)))
    int k = start;
    if ((k & 1) && k < end) {
        int2 e0 = adj[k];
        unsigned v0 = LDN(e0.x);
        ACC_WORD(v0, *reinterpret_cast<__half2*>(&e0.y));
        k++;
    }
    for (; k + 8 <= end; k += 8) {
        const int4* p4 = reinterpret_cast<const int4*>(adj + k);
        int4 A = p4[0];
        int4 B = p4[1];
        int4 C = p4[2];
        int4 D = p4[3];
        unsigned v0 = LDN(A.x);
        unsigned v1 = LDN(A.z);
        unsigned v2 = LDN(B.x);
        unsigned v3 = LDN(B.z);
        unsigned v4 = LDN(C.x);
        unsigned v5 = LDN(C.z);
        unsigned v6 = LDN(D.x);
        unsigned v7 = LDN(D.z);
        ACC_WORD(v0, *reinterpret_cast<__half2*>(&A.y));
        ACC_WORD(v1, *reinterpret_cast<__half2*>(&A.w));
        ACC_WORD(v2, *reinterpret_cast<__half2*>(&B.y));
        ACC_WORD(v3, *reinterpret_cast<__half2*>(&B.w));
        ACC_WORD(v4, *reinterpret_cast<__half2*>(&C.y));
        ACC_WORD(v5, *reinterpret_cast<__half2*>(&C.w));
        ACC_WORD(v6, *reinterpret_cast<__half2*>(&D.y));
        ACC_WORD(v7, *reinterpret_cast<__half2*>(&D.w));
    }
    if (k + 4 <= end) {
        const int4* p4 = reinterpret_cast<const int4*>(adj + k);
        int4 A = p4[0];
        int4 B = p4[1];
        unsigned v0 = LDN(A.x);
        unsigned v1 = LDN(A.z);
        unsigned v2 = LDN(B.x);
        unsigned v3 = LDN(B.z);
        ACC_WORD(v0, *reinterpret_cast<__half2*>(&A.y));
        ACC_WORD(v1, *reinterpret_cast<__half2*>(&A.w));
        ACC_WORD(v2, *reinterpret_cast<__half2*>(&B.y));
        ACC_WORD(v3, *reinterpret_cast<__half2*>(&B.w));
        k += 4;
    }
    for (; k < end; k++) {
        int2 e0 = adj[k];
        unsigned v0 = LDN(e0.x);
        ACC_WORD(v0, *reinterpret_cast<__half2*>(&e0.y));
    }
    #undef LDN
}

// ---------------- init: zero degrees + barrier counters + loss ----------------
__global__ void init_kernel(float* __restrict__ loss_out, int has_loss) {
    int t = blockIdx.x * 256 + threadIdx.x;
    if (t < U_N) g_deg_u[t] = 0;
    if (t < I_N) g_deg_i[t] = 0;
    if (t < 2) g_cnt[t] = 0;
    if (t == 0 && has_loss) *loss_out = 0.0f;
}

// ---------------- degree (4 edges/thread, int4 index loads) ----------------
__global__ void degree_kernel(const int4* __restrict__ u_idx4,
                              const int4* __restrict__ i_idx4) {
    int t = blockIdx.x * blockDim.x + threadIdx.x;
    if (t >= E_N / 4) return;
    int4 u = u_idx4[t];
    int4 i = i_idx4[t];
    atomicAdd(&g_deg_u[u.x], 1); atomicAdd(&g_deg_u[u.y], 1);
    atomicAdd(&g_deg_u[u.z], 1); atomicAdd(&g_deg_u[u.w], 1);
    atomicAdd(&g_deg_i[i.x], 1); atomicAdd(&g_deg_i[i.y], 1);
    atomicAdd(&g_deg_i[i.z], 1); atomicAdd(&g_deg_i[i.w], 1);
}

// ---------------- grid barrier (147 co-resident blocks) ----------------
__device__ __forceinline__ void grid_barrier(int id) {
    __syncthreads();
    __threadfence();
    if (threadIdx.x == 0) {
        atomicAdd(&g_cnt[id], 1u);
        while (*((volatile unsigned*)&g_cnt[id]) < (unsigned)NBLK) { }
    }
    __syncthreads();
    __threadfence();
}

// ---------------- fused 3-phase row-pointer scan (one 147-block launch) ----------------
__global__ void __launch_bounds__(256) scan_kernel() {
    bool isU = blockIdx.x < NCH_U;
    const int* deg = isU ? g_deg_u : g_deg_i;
    int* row       = isU ? g_row_u : g_row_i;
    int* cur       = isU ? g_cur_u : g_cur_i;
    int* part      = isU ? g_chunk_u : g_chunk_i;
    int  c         = isU ? blockIdx.x : blockIdx.x - NCH_U;
    int  n         = isU ? U_N : I_N;

    int base = c * CHUNK + threadIdx.x * 4;
    int lane = threadIdx.x & 31, w = threadIdx.x >> 5;
    __shared__ int ws[8];

    // ---- phase A: this chunk's total ----
    int d[4], e[4];
    int s = 0;
    #pragma unroll
    for (int j = 0; j < 4; j++) {
        int idx = base + j;
        d[j] = (idx < n) ? deg[idx] : 0;
        e[j] = s;
        s += d[j];
    }
    {
        int v = s;
        #pragma unroll
        for (int o = 16; o > 0; o >>= 1) v += __shfl_down_sync(0xFFFFFFFFu, v, o);
        if (lane == 0) ws[w] = v;
        __syncthreads();
        if (threadIdx.x < 8) {
            int x = ws[threadIdx.x];
            #pragma unroll
            for (int o = 4; o > 0; o >>= 1) x += __shfl_down_sync(0xFFu, x, o);
            if (threadIdx.x == 0) part[c] = x;
        }
    }
    grid_barrier(0);

    // ---- phase B: block 0 scans both partial arrays ----
    if (blockIdx.x == 0) {
        __shared__ int buf[256];
        int t = threadIdx.x;
        int v = (t < NCH_U) ? g_chunk_u[t] : 0;
        buf[t] = v; __syncthreads();
        #pragma unroll
        for (int o = 1; o < 256; o <<= 1) {
            int x = (t >= o) ? buf[t - o] : 0;
            __syncthreads(); buf[t] += x; __syncthreads();
        }
        if (t < NCH_U) g_chunk_u[t] = buf[t] - v;
        __syncthreads();
        int v2 = (t < NCH_I) ? g_chunk_i[t] : 0;
        buf[t] = v2; __syncthreads();
        #pragma unroll
        for (int o = 1; o < 256; o <<= 1) {
            int x = (t >= o) ? buf[t - o] : 0;
            __syncthreads(); buf[t] += x; __syncthreads();
        }
        if (t < NCH_I) g_chunk_i[t] = buf[t] - v2;
        if (t == 0) { g_row_u[U_N] = E_N; g_row_i[I_N] = E_N; }
    }
    grid_barrier(1);

    // ---- phase C: local exclusive scan + chunk base; init cursors ----
    int cbase = isU ? g_chunk_u[c] : g_chunk_i[c];
    int inc = s;
    #pragma unroll
    for (int o = 1; o < 32; o <<= 1) {
        int x = __shfl_up_sync(0xFFFFFFFFu, inc, o);
        if (lane >= o) inc += x;
    }
    __shared__ int ws2[8];
    if (lane == 31) ws2[w] = inc;
    __syncthreads();
    if (threadIdx.x < 8) {
        int v = ws2[threadIdx.x];
        #pragma unroll
        for (int o = 1; o < 8; o <<= 1) {
            int x = __shfl_up_sync(0xFFu, v, o);
            if ((int)threadIdx.x >= o) v += x;
        }
        ws2[threadIdx.x] = v;
    }
    __syncthreads();
    int excl = inc - s + (w > 0 ? ws2[w - 1] : 0) + cbase;
    #pragma unroll
    for (int j = 0; j < 4; j++) {
        int idx = base + j;
        if (idx < n) { int r = excl + e[j]; row[idx] = r; cur[idx] = r; }
    }
}

// ------- fused fill (CSR adjacency) + fp8 convert + acc_init (layer-0 term) -------
#define FILL_BLOCKS_EXACT ((E_N / 4 + 255) / 256)         // 1954
#define CONV_BLOCKS (((U_N + I_N) * 32 + 255) / 256)      // 18750
#define ACC_BLOCKS ((B_N * 32 + 255) / 256)               // 512

__global__ void fillconv_kernel(const int4* __restrict__ u_idx4,
                                const int4* __restrict__ i_idx4,
                                const float4* __restrict__ user_feat,
                                const float4* __restrict__ item_feat,
                                const int* __restrict__ ui,
                                const int* __restrict__ ii) {
    if (blockIdx.x < FILL_BLOCKS_EXACT) {
        int t = blockIdx.x * 256 + threadIdx.x;
        if (t >= E_N / 4) return;
        int4 u4 = u_idx4[t];
        int4 i4 = i_idx4[t];
        #pragma unroll
        for (int j = 0; j < 4; j++) {
            int u = (j == 0) ? u4.x : (j == 1) ? u4.y : (j == 2) ? u4.z : u4.w;
            int i = (j == 0) ? i4.x : (j == 1) ? i4.y : (j == 2) ? i4.z : i4.w;
            float nf = rsqrtf((float)g_deg_u[u] * (float)g_deg_i[i]);
            __half2 h2 = __half2half2(__float2half_rn(nf));
            int nb = *reinterpret_cast<int*>(&h2);
            int pu = atomicAdd(&g_cur_u[u], 1);
            g_adj_u[pu] = make_int2(i << 7, nb);   // byte offset of row
            int pi = atomicAdd(&g_cur_i[i], 1);
            g_adj_i[pi] = make_int2(u << 7, nb);
        }
        return;
    }
    if (blockIdx.x < FILL_BLOCKS_EXACT + CONV_BLOCKS) {
        int t = (blockIdx.x - FILL_BLOCKS_EXACT) * 256 + threadIdx.x;
        const int nu = U_N * 32;
        const int ni = I_N * 32;
        float4 v; unsigned* dst; int o;
        if (t < nu)           { v = user_feat[t]; dst = g_f8_u[0]; o = t; }
        else if (t < nu + ni) { o = t - nu; v = item_feat[o]; dst = g_f8_i[0]; }
        else return;
        __half2 lo = __floats2half2_rn(v.x * FP8_SCALE, v.y * FP8_SCALE);
        __half2 hi = __floats2half2_rn(v.z * FP8_SCALE, v.w * FP8_SCALE);
        dst[o] = pack_f8x4(lo, hi);
        return;
    }
    // acc_init: layer-0 term from exact fp32 inputs
    int t = (blockIdx.x - FILL_BLOCKS_EXACT - CONV_BLOCKS) * 256 + threadIdx.x;
    if (t >= B_N * 32) return;
    int b = t >> 5;
    int dd = t & 31;
    ((float4*)g_acc_u)[t] = user_feat[(size_t)ui[b] * 32 + dd];
    ((float4*)g_acc_i)[t] = item_feat[(size_t)ii[b] * 32 + dd];
}

// ---------------- gather: warp per row (R12 layout); fused acc warps ----------------
__global__ void gather_kernel(const unsigned* __restrict__ s8_u,
                              const unsigned* __restrict__ s8_i,
                              unsigned* __restrict__ d8_u,
                              unsigned* __restrict__ d8_i,
                              const int* __restrict__ ui,
                              const int* __restrict__ ii,
                              float acc_coef) {
    int w = (blockIdx.x * blockDim.x + threadIdx.x) >> 5;
    int lane = threadIdx.x & 31;

    if (w >= U_N + I_N) {
        int b = w - (U_N + I_N);
        if (b >= B_N || acc_coef == 0.0f) return;
        float c = acc_coef * FP8_INV;
        int t = b * 32 + lane;
        unsigned q = s8_u[(size_t)ui[b] * 32 + lane];
        float2 p = __half22float2(e4m3x2_to_h2((unsigned short)(q & 0xFFFFu)));
        float2 r = __half22float2(e4m3x2_to_h2((unsigned short)(q >> 16)));
        float4 a = ((float4*)g_acc_u)[t];
        a.x += c * p.x; a.y += c * p.y; a.z += c * r.x; a.w += c * r.y;
        ((float4*)g_acc_u)[t] = a;
        unsigned q2 = s8_i[(size_t)ii[b] * 32 + lane];
        p = __half22float2(e4m3x2_to_h2((unsigned short)(q2 & 0xFFFFu)));
        r = __half22float2(e4m3x2_to_h2((unsigned short)(q2 >> 16)));
        float4 ai = ((float4*)g_acc_i)[t];
        ai.x += c * p.x; ai.y += c * p.y; ai.z += c * r.x; ai.w += c * r.y;
        ((float4*)g_acc_i)[t] = ai;
        return;
    }

    const int* rp; const int2* adj;
    const unsigned* src; const unsigned* self; unsigned* dst; int d;
    if (w < U_N) {
        d = w; rp = g_row_u; adj = g_adj_u;
        src = s8_i; self = s8_u; dst = d8_u;
    } else {
        d = w - U_N; rp = g_row_i; adj = g_adj_i;
        src = s8_u; self = s8_i; dst = d8_i;
    }

    int start = rp[d];
    int end   = rp[d + 1];
    const char* lane_base = reinterpret_cast<const char*>(src) + ((unsigned)lane << 2);

    unsigned sv = self[(size_t)d * 32 + lane];
    __half2 a01 = e4m3x2_to_h2((unsigned short)(sv & 0xFFFFu));
    __half2 a23 = e4m3x2_to_h2((unsigned short)(sv >> 16));

    row_gather(adj, lane_base, start, end, a01, a23);

    dst[(size_t)d * 32 + lane] = pack_f8x4(a01, a23);
}

// ---------------- fused final: on-the-fly layer-3 rows + layers 2,3 acc + BCE ----------------
__global__ void final_kernel(const unsigned* __restrict__ h2_u,
                             const unsigned* __restrict__ h2_i,
                             const int* __restrict__ ui,
                             const int* __restrict__ ii,
                             const float* __restrict__ labels,
                             float* __restrict__ pred_out,
                             float* __restrict__ loss_out,
                             int has_loss) {
    int b = (blockIdx.x * blockDim.x + threadIdx.x) >> 5;
    int lane = threadIdx.x & 31;
    if (b >= B_N) return;

    const float c2 = (1.0f / 3.0f) * FP8_INV;
    const float c3 = 0.25f * FP8_INV;
    int t = b * 32 + lane;

    // ---- user side ----
    int ru = ui[b];
    unsigned svu = h2_u[(size_t)ru * 32 + lane];
    __half2 a01 = e4m3x2_to_h2((unsigned short)(svu & 0xFFFFu));
    __half2 a23 = e4m3x2_to_h2((unsigned short)(svu >> 16));
    float2 su0 = __half22float2(a01);
    float2 su1 = __half22float2(a23);
    {
        const char* lane_base = reinterpret_cast<const char*>(h2_i) + ((unsigned)lane << 2);
        row_gather(g_adj_u, lane_base, g_row_u[ru], g_row_u[ru + 1], a01, a23);
    }
    float2 r0 = __half22float2(a01);
    float2 r1 = __half22float2(a23);
    float4 au = ((const float4*)g_acc_u)[t];
    au.x += c2 * su0.x + c3 * r0.x;
    au.y += c2 * su0.y + c3 * r0.y;
    au.z += c2 * su1.x + c3 * r1.x;
    au.w += c2 * su1.y + c3 * r1.y;

    // ---- item side ----
    int ri = ii[b];
    unsigned svi = h2_i[(size_t)ri * 32 + lane];
    a01 = e4m3x2_to_h2((unsigned short)(svi & 0xFFFFu));
    a23 = e4m3x2_to_h2((unsigned short)(svi >> 16));
    float2 si0 = __half22float2(a01);
    float2 si1 = __half22float2(a23);
    {
        const char* lane_base = reinterpret_cast<const char*>(h2_u) + ((unsigned)lane << 2);
        row_gather(g_adj_i, lane_base, g_row_i[ri], g_row_i[ri + 1], a01, a23);
    }
    r0 = __half22float2(a01);
    r1 = __half22float2(a23);
    float4 ai = ((const float4*)g_acc_i)[t];
    ai.x += c2 * si0.x + c3 * r0.x;
    ai.y += c2 * si0.y + c3 * r0.y;
    ai.z += c2 * si1.x + c3 * r1.x;
    ai.w += c2 * si1.y + c3 * r1.y;

    // ---- dot + sigmoid + BCE ----
    float s = au.x * ai.x + au.y * ai.y + au.z * ai.z + au.w * ai.w;
    #pragma unroll
    for (int o = 16; o > 0; o >>= 1)
        s += __shfl_down_sync(0xFFFFFFFFu, s, o);

    if (lane == 0) {
        float z = 1.0f / (1.0f + expf(-s));
        pred_out[b] = z;
        if (has_loss) {
            float lbl = labels[b];
            float term = fmaxf(z, 0.0f) - z * lbl + log1pf(expf(-fabsf(z)));
            atomicAdd(loss_out, term * (1.0f / (float)B_N));
        }
    }
}

// ---------------- host launch ----------------
extern "C" void kernel_launch(void* const* d_in, const int* in_sizes, int n_in,
                              void* d_out, int out_size) {
    const float* user_feat = (const float*)d_in[0];
    const float* item_feat = (const float*)d_in[1];
    const int*   u_idx     = (const int*)d_in[2];
    const int*   i_idx     = (const int*)d_in[3];
    const int*   ui        = (const int*)d_in[4];
    const int*   ii        = (const int*)d_in[5];
    const float* labels    = (const float*)d_in[6];

    float* out = (float*)d_out;
    int has_loss = (out_size > B_N) ? 1 : 0;
    float* pred_out = out + (out_size - B_N);
    float* loss_out = out;

    unsigned *hu_base, *hi_base;
    cudaGetSymbolAddress((void**)&hu_base, g_f8_u);
    cudaGetSymbolAddress((void**)&hi_base, g_f8_i);
    unsigned* hu[2] = { hu_base, hu_base + (size_t)U_N * 32 };
    unsigned* hi[2] = { hi_base, hi_base + (size_t)I_N * 32 };

    const int T = 256;
    const int init_blocks = (U_N + 255) / 256;
    const int deg_blocks = (E_N / 4 + T - 1) / T;
    const int fillconv_blocks = FILL_BLOCKS_EXACT + CONV_BLOCKS + ACC_BLOCKS;
    const int gather_blocks = ((U_N + I_N + B_N) * 32 + T - 1) / T;

    // 1) init: zero degrees + barrier counters + loss
    init_kernel<<<init_blocks, T>>>(loss_out, has_loss);
    // 2) degrees (wide)
    degree_kernel<<<deg_blocks, T>>>((const int4*)u_idx, (const int4*)i_idx);
    // 3) fused 3-phase row-pointer scan (147 co-resident blocks, 2 grid barriers)
    scan_kernel<<<NBLK, T>>>();
    // 4) fused CSR fill + fp8 convert + acc layer-0 init (all wide, independent)
    fillconv_kernel<<<fillconv_blocks, T>>>((const int4*)u_idx, (const int4*)i_idx,
                                            (const float4*)user_feat,
                                            (const float4*)item_feat,
                                            ui, ii);

    // 5) TWO full propagation layers (h1, h2); layer-1 acc fused into gather #2
    gather_kernel<<<gather_blocks, T>>>(hu[0], hi[0], hu[1], hi[1],
                                        ui, ii, 0.0f);
    gather_kernel<<<gather_blocks, T>>>(hu[1], hi[1], hu[0], hi[0],
                                        ui, ii, 0.5f);
    // hu[0]/hi[0] now hold h2

    // 6) fused final: layer-2 acc + on-the-fly layer-3 rows + dot + sigmoid + BCE
    final_kernel<<<(B_N * 32 + T - 1) / T, T>>>(hu[0], hi[0],
                                                ui, ii, labels,
                                                pred_out, loss_out, has_loss);
}